// round 9
// baseline (speedup 1.0000x reference)
#include <cuda_runtime.h>
#include <math.h>

#define N_NODESC 100000
#define N_EDGESC 3200000
#define IN_DIMC  128
#define H1C      8
#define D1C      64     // H1*F1
#define NCC      40
#define NEG      0.2f
#define NB_SCAN  196    // ceil(100000/512)
#define FULLM    0xffffffffu

// ---------------- device scratch (no allocation allowed) ----------------
__device__ float    g_h1 [N_NODESC * D1C];
__device__ float    g_e1s[N_NODESC * H1C];
__device__ float    g_e1d[N_NODESC * H1C];
__device__ float    g_x2 [N_NODESC * D1C];
__device__ float    g_h2 [N_NODESC * NCC];
__device__ float    g_e2s[N_NODESC];
__device__ float    g_e2d[N_NODESC];
__device__ int      g_deg [N_NODESC];
__device__ int      g_cur [N_NODESC];
__device__ int      g_off [N_NODESC];
__device__ int      g_scan[N_NODESC];
__device__ int      g_bsum[NB_SCAN];
__device__ int      g_boff[NB_SCAN];
__device__ int      g_csr [N_EDGESC];
__device__ int      g_is64;

__device__ __forceinline__ float lrelu(float v) { return v > 0.f ? v : NEG * v; }

// ------- adjacency dtype probe: int64 iff first 256 int64s are valid ----
__global__ void k_detect(const long long* __restrict__ adj) {
    if (threadIdx.x == 0) {
        int ok = 1;
        for (int i = 0; i < 256; i++) {
            long long v = adj[i];
            if (v < 0 || v >= N_NODESC) { ok = 0; break; }
        }
        g_is64 = ok;
    }
}

__device__ __forceinline__ int load_idx(const void* adj, long long pos) {
    return g_is64 ? (int)((const long long*)adj)[pos] : ((const int*)adj)[pos];
}

// ---------------- init: zero degree ------------------------------------
__global__ void k_init() {
    int i = blockIdx.x * blockDim.x + threadIdx.x;
    if (i < N_NODESC) g_deg[i] = 0;
}

// ---------------- CSR build: histogram, scan, fill ----------------------
__global__ void k_hist(const void* __restrict__ adj) {
    int i = blockIdx.x * blockDim.x + threadIdx.x;
    if (i >= N_EDGESC) return;
    int d = load_idx(adj, (long long)N_EDGESC + i);
    atomicAdd(&g_deg[d], 1);
}

__global__ __launch_bounds__(512) void k_scan1() {
    __shared__ int sh[512];
    int t = threadIdx.x;
    int i = blockIdx.x * 512 + t;
    int v = (i < N_NODESC) ? g_deg[i] : 0;
    sh[t] = v;
    __syncthreads();
    #pragma unroll
    for (int off = 1; off < 512; off <<= 1) {
        int add = (t >= off) ? sh[t - off] : 0;
        __syncthreads();
        sh[t] += add;
        __syncthreads();
    }
    if (i < N_NODESC) g_scan[i] = sh[t];
    if (t == 511) g_bsum[blockIdx.x] = sh[511];
}

__global__ __launch_bounds__(256) void k_scan2() {
    __shared__ int sh[256];
    int t = threadIdx.x;
    sh[t] = (t < NB_SCAN) ? g_bsum[t] : 0;
    __syncthreads();
    #pragma unroll
    for (int off = 1; off < 256; off <<= 1) {
        int add = (t >= off) ? sh[t - off] : 0;
        __syncthreads();
        sh[t] += add;
        __syncthreads();
    }
    if (t < NB_SCAN) g_boff[t] = sh[t];
}

__global__ void k_scan3() {
    int i = blockIdx.x * blockDim.x + threadIdx.x;
    if (i >= N_NODESC) return;
    int b = i >> 9;
    int base = (b > 0) ? g_boff[b - 1] : 0;
    int start = g_scan[i] - g_deg[i] + base;    // exclusive global offset
    g_off[i] = start;
    g_cur[i] = start;                           // absolute running cursor
}

__global__ void k_fill(const void* __restrict__ adj) {
    int i = blockIdx.x * blockDim.x + threadIdx.x;
    if (i >= N_EDGESC) return;
    int s = load_idx(adj, i);
    int d = load_idx(adj, (long long)N_EDGESC + i);
    int pos = atomicAdd(&g_cur[d], 1);
    g_csr[pos] = s;
}

// ------- GEMM1 + fused e1s/e1d: h1 = x @ W1 (100000x128 @ 128x64) -------
// 256 threads, tile 128 nodes x 64 cols, per-thread 4 nodes x 8 cols.
// Thread (ng,cg) holds full head cg for its 4 nodes -> e1s/e1d are local dots.
__global__ __launch_bounds__(256) void k_gemm1(const float* __restrict__ x,
                                               const float* __restrict__ W1,
                                               const float* __restrict__ a1s,
                                               const float* __restrict__ a1d) {
    __shared__ float xs[32][132];   // [k][node], padded
    __shared__ float ws[32][64];    // [k][col]
    const int t = threadIdx.x;
    const int base = blockIdx.x * 128;
    const int ng = t >> 3;          // 0..31, 4 nodes each
    const int cg = t & 7;           // 0..7 = head, 8 cols each

    float acc[4][8];
    #pragma unroll
    for (int i = 0; i < 4; i++)
        #pragma unroll
        for (int j = 0; j < 8; j++) acc[i][j] = 0.f;

    for (int kc = 0; kc < IN_DIMC; kc += 32) {
        // W chunk: 32x64 = 512 float4, 2 per thread
        for (int i = t; i < 512; i += 256) {
            int k = i >> 4, j = (i & 15) << 2;
            float4 v = *(const float4*)&W1[(kc + k) * D1C + j];
            ws[k][j] = v.x; ws[k][j+1] = v.y; ws[k][j+2] = v.z; ws[k][j+3] = v.w;
        }
        // X chunk transposed: 128 nodes x 32 k = 1024 float4, 4 per thread
        for (int i = t; i < 1024; i += 256) {
            int node = i >> 3, kq = i & 7;
            int gn = base + node;
            float4 v = make_float4(0.f, 0.f, 0.f, 0.f);
            if (gn < N_NODESC) v = *(const float4*)&x[gn * IN_DIMC + kc + kq * 4];
            int k = kq * 4;
            xs[k][node] = v.x; xs[k+1][node] = v.y; xs[k+2][node] = v.z; xs[k+3][node] = v.w;
        }
        __syncthreads();
        #pragma unroll 8
        for (int k = 0; k < 32; k++) {
            float4 xa = *(const float4*)&xs[k][ng * 4];
            float4 wa = *(const float4*)&ws[k][cg * 8];
            float4 wb = *(const float4*)&ws[k][cg * 8 + 4];
            float xv[4] = {xa.x, xa.y, xa.z, xa.w};
            float wv[8] = {wa.x, wa.y, wa.z, wa.w, wb.x, wb.y, wb.z, wb.w};
            #pragma unroll
            for (int i = 0; i < 4; i++)
                #pragma unroll
                for (int j = 0; j < 8; j++) acc[i][j] += xv[i] * wv[j];
        }
        __syncthreads();
    }

    float asv[8], adv[8];
    #pragma unroll
    for (int j = 0; j < 8; j++) { asv[j] = a1s[cg * 8 + j]; adv[j] = a1d[cg * 8 + j]; }

    #pragma unroll
    for (int i = 0; i < 4; i++) {
        int gn = base + ng * 4 + i;
        if (gn < N_NODESC) {
            *(float4*)&g_h1[gn * D1C + cg * 8]     = make_float4(acc[i][0], acc[i][1], acc[i][2], acc[i][3]);
            *(float4*)&g_h1[gn * D1C + cg * 8 + 4] = make_float4(acc[i][4], acc[i][5], acc[i][6], acc[i][7]);
            float es = 0.f, ev = 0.f;
            #pragma unroll
            for (int j = 0; j < 8; j++) { es += acc[i][j] * asv[j]; ev += acc[i][j] * adv[j]; }
            g_e1s[gn * H1C + cg] = es;
            g_e1d[gn * H1C + cg] = ev;
        }
    }
}

// -------- layer1 gather: warp per dst, fused softmax-norm + ELU ---------
// Coalesced csr chunk loads + shfl; unroll x4 with independent chains.
__global__ void k_agg1() {
    int d    = (blockIdx.x * blockDim.x + threadIdx.x) >> 5;
    int lane = threadIdx.x & 31;
    if (d >= N_NODESC) return;
    const int h8 = lane & 7;
    const int la = lane >> 3, lb = 4 + (lane >> 3);
    float ed = g_e1d[d * H1C + h8];

    // self loop
    float p = __expf(lrelu(g_e1s[d * H1C + h8] + ed));
    float psum = p;
    float pa = __shfl_sync(FULLM, p, la);
    float pb = __shfl_sync(FULLM, p, lb);
    float acc0 = pa * g_h1[d * D1C + lane];
    float acc1 = pb * g_h1[d * D1C + 32 + lane];

    const int beg = g_off[d], n = g_deg[d];
    for (int j0 = 0; j0 < n; j0 += 32) {
        int idx = j0 + lane;
        int myS = (idx < n) ? g_csr[beg + idx] : 0;
        int lim = min(32, n - j0);
        int j = 0;
        for (; j + 3 < lim; j += 4) {
            int s0 = __shfl_sync(FULLM, myS, j);
            int s1 = __shfl_sync(FULLM, myS, j + 1);
            int s2 = __shfl_sync(FULLM, myS, j + 2);
            int s3 = __shfl_sync(FULLM, myS, j + 3);
            float es0 = g_e1s[s0 * H1C + h8];
            float es1 = g_e1s[s1 * H1C + h8];
            float es2 = g_e1s[s2 * H1C + h8];
            float es3 = g_e1s[s3 * H1C + h8];
            float p0 = __expf(lrelu(es0 + ed));
            float p1 = __expf(lrelu(es1 + ed));
            float p2 = __expf(lrelu(es2 + ed));
            float p3 = __expf(lrelu(es3 + ed));
            psum += (p0 + p1) + (p2 + p3);
            float pa0 = __shfl_sync(FULLM, p0, la), pb0 = __shfl_sync(FULLM, p0, lb);
            float pa1 = __shfl_sync(FULLM, p1, la), pb1 = __shfl_sync(FULLM, p1, lb);
            float pa2 = __shfl_sync(FULLM, p2, la), pb2 = __shfl_sync(FULLM, p2, lb);
            float pa3 = __shfl_sync(FULLM, p3, la), pb3 = __shfl_sync(FULLM, p3, lb);
            float h00 = g_h1[s0 * D1C + lane],      h01 = g_h1[s0 * D1C + 32 + lane];
            float h10 = g_h1[s1 * D1C + lane],      h11 = g_h1[s1 * D1C + 32 + lane];
            float h20 = g_h1[s2 * D1C + lane],      h21 = g_h1[s2 * D1C + 32 + lane];
            float h30 = g_h1[s3 * D1C + lane],      h31 = g_h1[s3 * D1C + 32 + lane];
            acc0 += (pa0 * h00 + pa1 * h10) + (pa2 * h20 + pa3 * h30);
            acc1 += (pb0 * h01 + pb1 * h11) + (pb2 * h21 + pb3 * h31);
        }
        for (; j < lim; j++) {
            int s0 = __shfl_sync(FULLM, myS, j);
            float p0 = __expf(lrelu(g_e1s[s0 * H1C + h8] + ed));
            psum += p0;
            float pa0 = __shfl_sync(FULLM, p0, la);
            float pb0 = __shfl_sync(FULLM, p0, lb);
            acc0 += pa0 * g_h1[s0 * D1C + lane];
            acc1 += pb0 * g_h1[s0 * D1C + 32 + lane];
        }
    }
    float sa = __shfl_sync(FULLM, psum, la);
    float sb = __shfl_sync(FULLM, psum, lb);
    float v0 = acc0 / sa, v1 = acc1 / sb;
    g_x2[d * D1C + lane]      = v0 > 0.f ? v0 : (__expf(v0) - 1.f);
    g_x2[d * D1C + 32 + lane] = v1 > 0.f ? v1 : (__expf(v1) - 1.f);
}

// -------- GEMM2 + fused e2s/e2d: h2 = x2 @ W2 (100000x64 @ 64x40) -------
__global__ __launch_bounds__(320) void k_gemm2(const float* __restrict__ W2,
                                               const float* __restrict__ a2s,
                                               const float* __restrict__ a2d) {
    __shared__ float xs[8][D1C];
    __shared__ float ws[D1C][NCC];
    __shared__ float rs[8][NCC];
    __shared__ float rd[8][NCC];
    const int t = threadIdx.x;
    const int base = blockIdx.x * 8;
    for (int i = t; i < D1C * NCC; i += 320) ws[i / NCC][i % NCC] = W2[i];
    for (int i = t; i < 8 * D1C; i += 320) {
        int n = i >> 6, j = i & 63;
        xs[n][j] = g_x2[(base + n) * D1C + j];
    }
    __syncthreads();
    const int n = t / NCC, c = t % NCC;
    float acc = 0.f;
    #pragma unroll 8
    for (int k = 0; k < D1C; k++) acc += xs[n][k] * ws[k][c];
    g_h2[(base + n) * NCC + c] = acc;
    rs[n][c] = acc * a2s[c];
    rd[n][c] = acc * a2d[c];
    __syncthreads();
    if (t < 8) {
        float sv = 0.f, dv = 0.f;
        #pragma unroll 8
        for (int c2 = 0; c2 < NCC; c2++) { sv += rs[t][c2]; dv += rd[t][c2]; }
        g_e2s[base + t] = sv;
        g_e2d[base + t] = dv;
    }
}

// -------- layer2 gather + log_softmax, warp per dst ---------------------
__global__ void k_agg2(float* __restrict__ out) {
    int d    = (blockIdx.x * blockDim.x + threadIdx.x) >> 5;
    int lane = threadIdx.x & 31;
    if (d >= N_NODESC) return;
    float ed = g_e2d[d];

    float p = __expf(lrelu(g_e2s[d] + ed));     // self loop
    float psum = p;
    float acc0 = p * g_h2[d * NCC + lane];
    float acc1 = (lane < 8) ? p * g_h2[d * NCC + 32 + lane] : 0.f;

    const int beg = g_off[d], n = g_deg[d];
    for (int j0 = 0; j0 < n; j0 += 32) {
        int idx = j0 + lane;
        int myS = (idx < n) ? g_csr[beg + idx] : 0;
        int lim = min(32, n - j0);
        int j = 0;
        for (; j + 3 < lim; j += 4) {
            int s0 = __shfl_sync(FULLM, myS, j);
            int s1 = __shfl_sync(FULLM, myS, j + 1);
            int s2 = __shfl_sync(FULLM, myS, j + 2);
            int s3 = __shfl_sync(FULLM, myS, j + 3);
            float p0 = __expf(lrelu(g_e2s[s0] + ed));
            float p1 = __expf(lrelu(g_e2s[s1] + ed));
            float p2 = __expf(lrelu(g_e2s[s2] + ed));
            float p3 = __expf(lrelu(g_e2s[s3] + ed));
            psum += (p0 + p1) + (p2 + p3);
            float h00 = g_h2[s0 * NCC + lane];
            float h10 = g_h2[s1 * NCC + lane];
            float h20 = g_h2[s2 * NCC + lane];
            float h30 = g_h2[s3 * NCC + lane];
            acc0 += (p0 * h00 + p1 * h10) + (p2 * h20 + p3 * h30);
            if (lane < 8) {
                float h01 = g_h2[s0 * NCC + 32 + lane];
                float h11 = g_h2[s1 * NCC + 32 + lane];
                float h21 = g_h2[s2 * NCC + 32 + lane];
                float h31 = g_h2[s3 * NCC + 32 + lane];
                acc1 += (p0 * h01 + p1 * h11) + (p2 * h21 + p3 * h31);
            }
        }
        for (; j < lim; j++) {
            int s0 = __shfl_sync(FULLM, myS, j);
            float p0 = __expf(lrelu(g_e2s[s0] + ed));
            psum += p0;
            acc0 += p0 * g_h2[s0 * NCC + lane];
            if (lane < 8) acc1 += p0 * g_h2[s0 * NCC + 32 + lane];
        }
    }
    float inv = 1.f / psum;
    float l1 = acc0 * inv;
    float l2 = (lane < 8) ? acc1 * inv : -1e30f;
    float m = fmaxf(l1, l2);
    #pragma unroll
    for (int o = 16; o; o >>= 1) m = fmaxf(m, __shfl_xor_sync(FULLM, m, o));
    float se = __expf(l1 - m) + ((lane < 8) ? __expf(l2 - m) : 0.f);
    #pragma unroll
    for (int o = 16; o; o >>= 1) se += __shfl_xor_sync(FULLM, se, o);
    float lse = m + logf(se);
    out[d * NCC + lane] = l1 - lse;
    if (lane < 8) out[d * NCC + 32 + lane] = l2 - lse;
}

// ------------------------------------------------------------------------
extern "C" void kernel_launch(void* const* d_in, const int* in_sizes, int n_in,
                              void* d_out, int out_size) {
    const float* x   = (const float*)d_in[0];
    const void*  adj = d_in[1];
    const float* W1  = (const float*)d_in[2];
    const float* a1s = (const float*)d_in[3];
    const float* a1d = (const float*)d_in[4];
    const float* W2  = (const float*)d_in[5];
    const float* a2s = (const float*)d_in[6];
    const float* a2d = (const float*)d_in[7];
    float* out = (float*)d_out;

    const int eg = (N_EDGESC + 255) / 256;      // 12500
    const int ng = (N_NODESC + 255) / 256;      // 391
    const int wg = N_NODESC / 8;                // 12500 (warp per node)

    k_detect <<<1, 32>>>((const long long*)adj);            // 0
    k_init   <<<ng, 256>>>();                               // 1
    k_hist   <<<eg, 256>>>(adj);                            // 2
    k_gemm1  <<<(N_NODESC + 127) / 128, 256>>>(x, W1, a1s, a1d);  // 3 <- profiled
    k_scan1  <<<NB_SCAN, 512>>>();                          // 4
    k_scan2  <<<1, 256>>>();                                // 5
    k_scan3  <<<ng, 256>>>();                               // 6
    k_fill   <<<eg, 256>>>(adj);                            // 7
    k_agg1   <<<wg, 256>>>();                               // 8
    k_gemm2  <<<(N_NODESC + 7) / 8, 320>>>(W2, a2s, a2d);   // 9
    k_agg2   <<<wg, 256>>>(out);                            // 10
}